// round 9
// baseline (speedup 1.0000x reference)
#include <cuda_runtime.h>
#include <math.h>
#include <stdint.h>

#define NSLICE 1088          // 64 * 17 slices per tensor
#define HW     16384         // 128 * 128
#define MAX_DIST 181.02f
#define NCTA 272             // 1088 / 4: exactly 4 pairs (8 slices) per CTA
#define NTH  1024
#define CHUNK_FLOATS 8192    // 32 KB chunks, 2 per slice (rows 0-63 / 64-127)
#define CHUNK_BYTES  32768
#define NRING 3              // 96 KB ring -> 2 CTAs/SM, 64 warps/SM

__device__ float g_acc = 0.0f;       // global loss accumulator (reset by last CTA)
__device__ unsigned int g_done = 0u; // CTA completion counter (reset by last CTA)

// ---------------------------------------------------------------------------
// mbarrier / bulk-copy / math helpers
// ---------------------------------------------------------------------------
__device__ __forceinline__ uint32_t smem_u32(const void* p) {
    return (uint32_t)__cvta_generic_to_shared(p);
}
__device__ __forceinline__ void mbar_init(uint32_t a, uint32_t cnt) {
    asm volatile("mbarrier.init.shared::cta.b64 [%0], %1;" :: "r"(a), "r"(cnt) : "memory");
}
__device__ __forceinline__ void mbar_arrive_expect(uint32_t a, uint32_t bytes) {
    asm volatile("mbarrier.arrive.expect_tx.shared::cta.b64 _, [%0], %1;"
                 :: "r"(a), "r"(bytes) : "memory");
}
__device__ __forceinline__ void bulk_g2s(uint32_t dst, const void* src,
                                         uint32_t bytes, uint32_t mbar) {
    asm volatile("cp.async.bulk.shared::cta.global.mbarrier::complete_tx::bytes "
                 "[%0], [%1], %2, [%3];"
                 :: "r"(dst), "l"(src), "r"(bytes), "r"(mbar) : "memory");
}
__device__ __forceinline__ void mbar_wait(uint32_t a, uint32_t parity) {
    asm volatile(
        "{\n\t.reg .pred P;\n\t"
        "WAIT_%=:\n\t"
        "mbarrier.try_wait.parity.shared::cta.b64 P, [%0], %1;\n\t"
        "@!P bra WAIT_%=;\n\t}"
        :: "r"(a), "r"(parity) : "memory");
}
__device__ __forceinline__ float fsqrt_approx(float x) {
    float r;
    asm("sqrt.approx.f32 %0, %1;" : "=f"(r) : "f"(x));
    return r;
}
__device__ __forceinline__ float max4(float4 q) {
    return fmaxf(fmaxf(q.x, q.y), fmaxf(q.z, q.w));
}

// ---------------------------------------------------------------------------
// Fused persistent kernel, 1024 threads, 2 CTAs/SM (64 warps/SM).
// Slice data lives in REGISTERS between passes: ring slots free at the first
// barrier -> refills issue ~2/3 of a slice earlier. 3 barriers/slice.
// Pass 1: value-only max; argmax via register rescan + shared atomicMin
// (exact lowest-flat-index tie-break). Pass 2: masked mean distance, MUFU
// sqrt. One atomicAdd per CTA; last CTA finalizes + resets globals.
// ---------------------------------------------------------------------------
__global__ void __launch_bounds__(NTH, 2) loss_kernel(const float* __restrict__ a,
                                                      const float* __restrict__ b,
                                                      float* __restrict__ out) {
    extern __shared__ float ring[];            // NRING * 8192 floats (96 KB)

    __shared__ __align__(8) unsigned long long mbar_store[NRING];
    __shared__ float s_v[32];
    __shared__ float s_s[32];
    __shared__ int   s_c[32];
    __shared__ int   s_idx;

    const int t = threadIdx.x;
    const int warp = t >> 5, lane = t & 31;
    const int cta = blockIdx.x;
    const int nchunk = 16;                     // 4 pairs = 8 slices = 16 chunks

    uint32_t mb[NRING];
    #pragma unroll
    for (int r = 0; r < NRING; ++r) mb[r] = smem_u32(&mbar_store[r]);
    if (t == 0) {
        #pragma unroll
        for (int r = 0; r < NRING; ++r) mbar_init(mb[r], 1);
    }
    __syncthreads();

    // chunk k: pair (k>>2), tensor ((k>>1)&1), half (k&1)
    auto chunk_src = [&](int k) -> const float* {
        int p = k >> 2, which = (k >> 1) & 1, half = k & 1;
        const float* base = which ? b : a;
        return base + (size_t)(cta + p * NCTA) * HW + (size_t)half * CHUNK_FLOATS;
    };

    if (t == 0) {                              // prefill all ring slots
        #pragma unroll
        for (int k = 0; k < NRING; ++k) {
            mbar_arrive_expect(mb[k], CHUNK_BYTES);
            bulk_g2s(smem_u32(ring + k * CHUNK_FLOATS), chunk_src(k),
                     CHUNK_BYTES, mb[k]);
        }
    }

    float acc = 0.0f;       // meaningful in t==0 only
    float prev_d = 0.0f;

    for (int m = 0; m < 8; ++m) {
        const int k0 = 2 * m, k1 = 2 * m + 1;
        const int slot0 = k0 % NRING, slot1 = k1 % NRING;

        // ---------- pass 1: load to regs, value-only max ---------------------
        float4 v0, v1, v2, v3;                 // 16 elements per thread
        mbar_wait(mb[slot0], (k0 / NRING) & 1);
        {
            const float4* p = (const float4*)(ring + slot0 * CHUNK_FLOATS);
            v0 = p[t];
            v1 = p[NTH + t];
        }
        mbar_wait(mb[slot1], (k1 / NRING) & 1);
        {
            const float4* p = (const float4*)(ring + slot1 * CHUNK_FLOATS);
            v2 = p[t];
            v3 = p[NTH + t];
        }
        const float mymax = fmaxf(fmaxf(max4(v0), max4(v1)),
                                  fmaxf(max4(v2), max4(v3)));
        float wmax = mymax;
        #pragma unroll
        for (int off = 16; off > 0; off >>= 1)
            wmax = fmaxf(wmax, __shfl_xor_sync(0xffffffffu, wmax, off));
        if (lane == 0) s_v[warp] = wmax;
        if (t == 0) s_idx = 0x7fffffff;
        __syncthreads();                       // S1: ring slots now free

        // refill freed slots ASAP (warp 1, overlaps the reductions below)
        if (t == 32) {
            if (k0 + NRING < nchunk) {
                mbar_arrive_expect(mb[slot0], CHUNK_BYTES);
                bulk_g2s(smem_u32(ring + slot0 * CHUNK_FLOATS),
                         chunk_src(k0 + NRING), CHUNK_BYTES, mb[slot0]);
            }
            if (k1 + NRING < nchunk) {
                mbar_arrive_expect(mb[slot1], CHUNK_BYTES);
                bulk_g2s(smem_u32(ring + slot1 * CHUNK_FLOATS),
                         chunk_src(k1 + NRING), CHUNK_BYTES, mb[slot1]);
            }
        }

        // block max, computed redundantly by every warp (no extra barrier)
        float bv = s_v[lane];
        #pragma unroll
        for (int off = 16; off > 0; off >>= 1)
            bv = fmaxf(bv, __shfl_xor_sync(0xffffffffu, bv, off));

        // rare path: holders of the max rescan their registers, lowest e wins
        if (mymax == bv) {
            const int eb = t << 2;
            int my_e = 0x7fffffff;
            // descending e order: final assignment is the lowest flat index
            if (v3.w == bv) my_e = 12288 + eb + 3;
            if (v3.z == bv) my_e = 12288 + eb + 2;
            if (v3.y == bv) my_e = 12288 + eb + 1;
            if (v3.x == bv) my_e = 12288 + eb;
            if (v2.w == bv) my_e =  8192 + eb + 3;
            if (v2.z == bv) my_e =  8192 + eb + 2;
            if (v2.y == bv) my_e =  8192 + eb + 1;
            if (v2.x == bv) my_e =  8192 + eb;
            if (v1.w == bv) my_e =  4096 + eb + 3;
            if (v1.z == bv) my_e =  4096 + eb + 2;
            if (v1.y == bv) my_e =  4096 + eb + 1;
            if (v1.x == bv) my_e =  4096 + eb;
            if (v0.w == bv) my_e =         eb + 3;
            if (v0.z == bv) my_e =         eb + 2;
            if (v0.y == bv) my_e =         eb + 1;
            if (v0.x == bv) my_e =         eb;
            atomicMin(&s_idx, my_e);
        }
        __syncthreads();                       // S2: s_idx final
        const int bi = s_idx;

        // ---------- pass 2: masked distance sum from registers ---------------
        const float thr = bv * 0.5f;
        const int ym = bi >> 7;
        const int xm = bi & 127;

        // x = 4*lane + j is slice-invariant per thread
        const int xb = (lane << 2) - xm;
        const float fdx2_0 = (float)(xb * xb);
        const float fdx2_1 = (float)((xb + 1) * (xb + 1));
        const float fdx2_2 = (float)((xb + 2) * (xb + 2));
        const float fdx2_3 = (float)((xb + 3) * (xb + 3));

        float sum = 0.0f;
        int   cnt = 0;
        // y(v0)=warp, y(v1)=32+warp, y(v2)=64+warp, y(v3)=96+warp
        #pragma unroll
        for (int q = 0; q < 4; ++q) {
            const float4 v = (q == 0) ? v0 : (q == 1) ? v1 : (q == 2) ? v2 : v3;
            const int dy = (q << 5) + warp - ym;
            const float fdy2 = (float)(dy * dy);
            float d0 = fsqrt_approx(fdy2 + fdx2_0);
            float d1 = fsqrt_approx(fdy2 + fdx2_1);
            float d2 = fsqrt_approx(fdy2 + fdx2_2);
            float d3 = fsqrt_approx(fdy2 + fdx2_3);
            if (v.x > thr) { sum += d0; ++cnt; }
            if (v.y > thr) { sum += d1; ++cnt; }
            if (v.z > thr) { sum += d2; ++cnt; }
            if (v.w > thr) { sum += d3; ++cnt; }
        }
        #pragma unroll
        for (int off = 16; off > 0; off >>= 1) {
            sum += __shfl_down_sync(0xffffffffu, sum, off);
            cnt += __shfl_down_sync(0xffffffffu, cnt, off);
        }
        if (lane == 0) { s_s[warp] = sum; s_c[warp] = cnt; }
        __syncthreads();                       // S3: all partials written

        // warp 0 reduces in parallel; shadowed by other warps entering pass 1
        if (warp == 0) {
            float S = s_s[lane];
            float C = (float)s_c[lane];
            #pragma unroll
            for (int off = 16; off > 0; off >>= 1) {
                S += __shfl_xor_sync(0xffffffffu, S, off);
                C += __shfl_xor_sync(0xffffffffu, C, off);
            }
            if (lane == 0) {
                float d;
                if (bv > 0.0f) {
                    d = (C > 0.0f) ? (S / C) / MAX_DIST : 1.0f;
                } else {
                    d = 0.0f;
                }
                if (m & 1) acc += fabsf(prev_d - d);   // pair done: |d_a - d_b|
                else       prev_d = d;
            }
        }
        // s_v/s_s/s_idx rewrites of the next slice are separated from all
        // reads of this slice by S1..S3 of the next iteration.
    }

    // ---------- fused finalize: one atomic per CTA; last CTA writes + resets
    if (t == 0) {
        atomicAdd(&g_acc, acc);
        __threadfence();
        unsigned int v = atomicAdd(&g_done, 1u);
        if (v == NCTA - 1) {
            float total = atomicAdd(&g_acc, 0.0f);   // serialized read after all adds
            out[0] = total / 17.0f / 64.0f;
            g_acc = 0.0f;                            // restore invariant for next run
            __threadfence();
            g_done = 0u;
        }
    }
}

extern "C" void kernel_launch(void* const* d_in, const int* in_sizes, int n_in,
                              void* d_out, int out_size) {
    const float* a = (const float*)d_in[0];   // output heatmaps [64,17,128,128] f32
    const float* b = (const float*)d_in[1];   // target heatmaps [64,17,128,128] f32
    (void)in_sizes; (void)n_in; (void)out_size;

    const int smem_bytes = NRING * CHUNK_BYTES;   // 96 KB

    static bool attr_set = false;
    if (!attr_set) {
        cudaFuncSetAttribute(loss_kernel,
                             cudaFuncAttributeMaxDynamicSharedMemorySize, smem_bytes);
        attr_set = true;
    }

    loss_kernel<<<NCTA, NTH, smem_bytes>>>(a, b, (float*)d_out);
}

// round 10
// speedup vs baseline: 1.2078x; 1.2078x over previous
#include <cuda_runtime.h>
#include <math.h>
#include <stdint.h>

#define NSLICE 1088          // 64 * 17 slices per tensor
#define HW     16384         // 128 * 128
#define MAX_DIST 181.02f
#define NCTA 148             // 1 CTA/SM, persistent
#define NTH  1024
#define CHUNK_FLOATS 8192    // 32 KB chunks, 2 per slice (rows 0-63 / 64-127)
#define CHUNK_BYTES  32768
#define NRING 6              // 192 KB ring -> ~2 slices of prefetch lead

__device__ float g_acc = 0.0f;       // global loss accumulator (reset by last CTA)
__device__ unsigned int g_done = 0u; // CTA completion counter (reset by last CTA)

// ---------------------------------------------------------------------------
// mbarrier / bulk-copy / math helpers
// ---------------------------------------------------------------------------
__device__ __forceinline__ uint32_t smem_u32(const void* p) {
    return (uint32_t)__cvta_generic_to_shared(p);
}
__device__ __forceinline__ void mbar_init(uint32_t a, uint32_t cnt) {
    asm volatile("mbarrier.init.shared::cta.b64 [%0], %1;" :: "r"(a), "r"(cnt) : "memory");
}
__device__ __forceinline__ void mbar_arrive_expect(uint32_t a, uint32_t bytes) {
    asm volatile("mbarrier.arrive.expect_tx.shared::cta.b64 _, [%0], %1;"
                 :: "r"(a), "r"(bytes) : "memory");
}
__device__ __forceinline__ void bulk_g2s(uint32_t dst, const void* src,
                                         uint32_t bytes, uint32_t mbar) {
    asm volatile("cp.async.bulk.shared::cta.global.mbarrier::complete_tx::bytes "
                 "[%0], [%1], %2, [%3];"
                 :: "r"(dst), "l"(src), "r"(bytes), "r"(mbar) : "memory");
}
__device__ __forceinline__ void mbar_wait(uint32_t a, uint32_t parity) {
    asm volatile(
        "{\n\t.reg .pred P;\n\t"
        "WAIT_%=:\n\t"
        "mbarrier.try_wait.parity.shared::cta.b64 P, [%0], %1;\n\t"
        "@!P bra WAIT_%=;\n\t}"
        :: "r"(a), "r"(parity) : "memory");
}
__device__ __forceinline__ float fsqrt_approx(float x) {
    float r;
    asm("sqrt.approx.f32 %0, %1;" : "=f"(r) : "f"(x));
    return r;
}
__device__ __forceinline__ float max4(float4 q) {
    return fmaxf(fmaxf(q.x, q.y), fmaxf(q.z, q.w));
}

// ---------------------------------------------------------------------------
// Fused persistent kernel: 1 CTA/SM, 1024 threads, 64 regs (no spills).
// Slice payload lives in registers between passes; ring slots free at the
// FIRST barrier, refills issued there -> ~2 slices of prefetch lead with the
// 6-deep ring. 3 barriers/slice. Value-only max; argmax via register rescan
// + shared atomicMin (exact lowest-flat-index tie-break). One atomicAdd per
// CTA; last CTA writes the loss and resets the globals.
// ---------------------------------------------------------------------------
__global__ void __launch_bounds__(NTH, 1) loss_kernel(const float* __restrict__ a,
                                                      const float* __restrict__ b,
                                                      float* __restrict__ out) {
    extern __shared__ float ring[];            // NRING * 8192 floats (192 KB)

    __shared__ __align__(8) unsigned long long mbar_store[NRING];
    __shared__ float s_v[32];
    __shared__ float s_s[32];
    __shared__ int   s_c[32];
    __shared__ int   s_idx;

    const int t = threadIdx.x;
    const int warp = t >> 5, lane = t & 31;
    const int cta = blockIdx.x;
    const int npair  = (NSLICE - cta + NCTA - 1) / NCTA;   // 7 or 8
    const int nslice = 2 * npair;
    const int nchunk = 2 * nslice;                          // 28 or 32

    const uint32_t mb0 = smem_u32(&mbar_store[0]);
    if (t == 0) {
        #pragma unroll
        for (int r = 0; r < NRING; ++r) mbar_init(mb0 + 8u * r, 1);
    }
    __syncthreads();

    // chunk k: pair (k>>2), tensor ((k>>1)&1), half (k&1)
    auto chunk_src = [&](int k) -> const float* {
        int p = k >> 2, which = (k >> 1) & 1, half = k & 1;
        const float* base = which ? b : a;
        return base + (size_t)(cta + p * NCTA) * HW + (size_t)half * CHUNK_FLOATS;
    };

    if (t == 0) {                              // prefill all ring slots
        #pragma unroll
        for (int k = 0; k < NRING; ++k) {
            mbar_arrive_expect(mb0 + 8u * k, CHUNK_BYTES);
            bulk_g2s(smem_u32(ring + k * CHUNK_FLOATS), chunk_src(k),
                     CHUNK_BYTES, mb0 + 8u * k);
        }
    }

    float acc = 0.0f;       // meaningful in t==0 only
    float prev_d = 0.0f;

    for (int m = 0; m < nslice; ++m) {
        const int k0 = 2 * m, k1 = 2 * m + 1;
        const int slot0 = k0 % NRING, slot1 = k1 % NRING;

        // ---------- pass 1: load to regs, value-only max ---------------------
        float4 v0, v1, v2, v3;                 // 16 elements per thread
        mbar_wait(mb0 + 8u * slot0, (k0 / NRING) & 1);
        {
            const float4* p = (const float4*)(ring + slot0 * CHUNK_FLOATS);
            v0 = p[t];
            v1 = p[NTH + t];
        }
        mbar_wait(mb0 + 8u * slot1, (k1 / NRING) & 1);
        {
            const float4* p = (const float4*)(ring + slot1 * CHUNK_FLOATS);
            v2 = p[t];
            v3 = p[NTH + t];
        }
        const float mymax = fmaxf(fmaxf(max4(v0), max4(v1)),
                                  fmaxf(max4(v2), max4(v3)));
        float wmax = mymax;
        #pragma unroll
        for (int off = 16; off > 0; off >>= 1)
            wmax = fmaxf(wmax, __shfl_xor_sync(0xffffffffu, wmax, off));
        if (lane == 0) s_v[warp] = wmax;
        if (t == 0) s_idx = 0x7fffffff;
        __syncthreads();                       // S1: ring slots now free

        // refill freed slots ASAP (warp 1; overlaps the reductions below)
        if (t == 32) {
            if (k0 + NRING < nchunk) {
                mbar_arrive_expect(mb0 + 8u * slot0, CHUNK_BYTES);
                bulk_g2s(smem_u32(ring + slot0 * CHUNK_FLOATS),
                         chunk_src(k0 + NRING), CHUNK_BYTES, mb0 + 8u * slot0);
            }
            if (k1 + NRING < nchunk) {
                mbar_arrive_expect(mb0 + 8u * slot1, CHUNK_BYTES);
                bulk_g2s(smem_u32(ring + slot1 * CHUNK_FLOATS),
                         chunk_src(k1 + NRING), CHUNK_BYTES, mb0 + 8u * slot1);
            }
        }

        // block max, computed redundantly by every warp (no extra barrier)
        float bv = s_v[lane];
        #pragma unroll
        for (int off = 16; off > 0; off >>= 1)
            bv = fmaxf(bv, __shfl_xor_sync(0xffffffffu, bv, off));

        // rare path: holders of the max rescan their registers, lowest e wins
        if (mymax == bv) {
            const int eb = t << 2;
            int my_e = 0x7fffffff;
            // descending e order: final assignment is the lowest flat index
            if (v3.w == bv) my_e = 12288 + eb + 3;
            if (v3.z == bv) my_e = 12288 + eb + 2;
            if (v3.y == bv) my_e = 12288 + eb + 1;
            if (v3.x == bv) my_e = 12288 + eb;
            if (v2.w == bv) my_e =  8192 + eb + 3;
            if (v2.z == bv) my_e =  8192 + eb + 2;
            if (v2.y == bv) my_e =  8192 + eb + 1;
            if (v2.x == bv) my_e =  8192 + eb;
            if (v1.w == bv) my_e =  4096 + eb + 3;
            if (v1.z == bv) my_e =  4096 + eb + 2;
            if (v1.y == bv) my_e =  4096 + eb + 1;
            if (v1.x == bv) my_e =  4096 + eb;
            if (v0.w == bv) my_e =         eb + 3;
            if (v0.z == bv) my_e =         eb + 2;
            if (v0.y == bv) my_e =         eb + 1;
            if (v0.x == bv) my_e =         eb;
            atomicMin(&s_idx, my_e);
        }
        __syncthreads();                       // S2: s_idx final
        const int bi = s_idx;

        // ---------- pass 2: masked distance sum from registers ---------------
        const float thr = bv * 0.5f;
        const int ym = bi >> 7;
        const int xm = bi & 127;

        // x = 4*lane + j is slice-invariant per thread
        const int xb = (lane << 2) - xm;
        const float fdx2_0 = (float)(xb * xb);
        const float fdx2_1 = (float)((xb + 1) * (xb + 1));
        const float fdx2_2 = (float)((xb + 2) * (xb + 2));
        const float fdx2_3 = (float)((xb + 3) * (xb + 3));

        float sum = 0.0f;
        int   cnt = 0;
        // y(v0)=warp, y(v1)=32+warp, y(v2)=64+warp, y(v3)=96+warp
        #pragma unroll
        for (int q = 0; q < 4; ++q) {
            const float4 v = (q == 0) ? v0 : (q == 1) ? v1 : (q == 2) ? v2 : v3;
            const int dy = (q << 5) + warp - ym;
            const float fdy2 = (float)(dy * dy);
            float d0 = fsqrt_approx(fdy2 + fdx2_0);
            float d1 = fsqrt_approx(fdy2 + fdx2_1);
            float d2 = fsqrt_approx(fdy2 + fdx2_2);
            float d3 = fsqrt_approx(fdy2 + fdx2_3);
            if (v.x > thr) { sum += d0; ++cnt; }
            if (v.y > thr) { sum += d1; ++cnt; }
            if (v.z > thr) { sum += d2; ++cnt; }
            if (v.w > thr) { sum += d3; ++cnt; }
        }
        #pragma unroll
        for (int off = 16; off > 0; off >>= 1) {
            sum += __shfl_down_sync(0xffffffffu, sum, off);
            cnt += __shfl_down_sync(0xffffffffu, cnt, off);
        }
        if (lane == 0) { s_s[warp] = sum; s_c[warp] = cnt; }
        __syncthreads();                       // S3: all partials written

        // warp 0 reduces in parallel; shadowed by other warps entering pass 1
        if (warp == 0) {
            float S = s_s[lane];
            float C = (float)s_c[lane];
            #pragma unroll
            for (int off = 16; off > 0; off >>= 1) {
                S += __shfl_xor_sync(0xffffffffu, S, off);
                C += __shfl_xor_sync(0xffffffffu, C, off);
            }
            if (lane == 0) {
                float d;
                if (bv > 0.0f) {
                    d = (C > 0.0f) ? (S / C) / MAX_DIST : 1.0f;
                } else {
                    d = 0.0f;
                }
                if (m & 1) acc += fabsf(prev_d - d);   // pair done: |d_a - d_b|
                else       prev_d = d;
            }
        }
        // s_v/s_s/s_idx rewrites of the next slice are separated from all
        // reads of this slice by S1..S3 of the next iteration.
    }

    // ---------- fused finalize: one atomic per CTA; last CTA writes + resets
    if (t == 0) {
        atomicAdd(&g_acc, acc);
        __threadfence();
        unsigned int v = atomicAdd(&g_done, 1u);
        if (v == NCTA - 1) {
            float total = atomicAdd(&g_acc, 0.0f);   // serialized read after all adds
            out[0] = total / 17.0f / 64.0f;
            g_acc = 0.0f;                            // restore invariant for next run
            __threadfence();
            g_done = 0u;
        }
    }
}

extern "C" void kernel_launch(void* const* d_in, const int* in_sizes, int n_in,
                              void* d_out, int out_size) {
    const float* a = (const float*)d_in[0];   // output heatmaps [64,17,128,128] f32
    const float* b = (const float*)d_in[1];   // target heatmaps [64,17,128,128] f32
    (void)in_sizes; (void)n_in; (void)out_size;

    const int smem_bytes = NRING * CHUNK_BYTES;   // 192 KB

    static bool attr_set = false;
    if (!attr_set) {
        cudaFuncSetAttribute(loss_kernel,
                             cudaFuncAttributeMaxDynamicSharedMemorySize, smem_bytes);
        attr_set = true;
    }

    loss_kernel<<<NCTA, NTH, smem_bytes>>>(a, b, (float*)d_out);
}

// round 11
// speedup vs baseline: 1.5122x; 1.2520x over previous
#include <cuda_runtime.h>
#include <math.h>
#include <stdint.h>

#define NSLICE 1088          // 64 * 17 slices per tensor
#define HW     16384         // 128 * 128
#define MAX_DIST 181.02f
#define NCTA 296             // 2 CTAs/SM
#define NTH  512
#define CHUNK_FLOATS 8192    // 32 KB chunks, 2 per slice (rows 0-63 / 64-127)
#define CHUNK_BYTES  32768
#define NRING 3              // 96 KB ring per CTA (192 KB/SM with 2 CTAs)

__device__ float g_acc = 0.0f;       // global loss accumulator (reset by last CTA)
__device__ unsigned int g_done = 0u; // CTA completion counter (reset by last CTA)

// ---------------------------------------------------------------------------
// mbarrier / bulk-copy / math helpers
// ---------------------------------------------------------------------------
__device__ __forceinline__ uint32_t smem_u32(const void* p) {
    return (uint32_t)__cvta_generic_to_shared(p);
}
__device__ __forceinline__ void mbar_init(uint32_t a, uint32_t cnt) {
    asm volatile("mbarrier.init.shared::cta.b64 [%0], %1;" :: "r"(a), "r"(cnt) : "memory");
}
__device__ __forceinline__ void mbar_arrive_expect(uint32_t a, uint32_t bytes) {
    asm volatile("mbarrier.arrive.expect_tx.shared::cta.b64 _, [%0], %1;"
                 :: "r"(a), "r"(bytes) : "memory");
}
__device__ __forceinline__ void bulk_g2s(uint32_t dst, const void* src,
                                         uint32_t bytes, uint32_t mbar) {
    asm volatile("cp.async.bulk.shared::cta.global.mbarrier::complete_tx::bytes "
                 "[%0], [%1], %2, [%3];"
                 :: "r"(dst), "l"(src), "r"(bytes), "r"(mbar) : "memory");
}
__device__ __forceinline__ void mbar_wait(uint32_t a, uint32_t parity) {
    asm volatile(
        "{\n\t.reg .pred P;\n\t"
        "WAIT_%=:\n\t"
        "mbarrier.try_wait.parity.shared::cta.b64 P, [%0], %1;\n\t"
        "@!P bra WAIT_%=;\n\t}"
        :: "r"(a), "r"(parity) : "memory");
}
__device__ __forceinline__ float fsqrt_approx(float x) {
    float r;
    asm("sqrt.approx.f32 %0, %1;" : "=f"(r) : "f"(x));
    return r;
}
__device__ __forceinline__ float max4(float4 q) {
    return fmaxf(fmaxf(q.x, q.y), fmaxf(q.z, q.w));
}

// ---------------------------------------------------------------------------
// Fused persistent kernel: 2 CTAs/SM x 512 threads (two independent pipelines
// per SM covering each other's stalls), 64 regs/thread budget. Slice payload
// (32 elems = 8 float4) in registers; ring slots free at the FIRST barrier,
// refilled by warp 1 there. 3 barriers/slice. Value-only max; argmax via rare
// register rescan + shared atomicMin (exact lowest-flat-index tie-break).
// One atomicAdd per CTA; last CTA writes the loss and resets the globals.
// ---------------------------------------------------------------------------
__global__ void __launch_bounds__(NTH, 2) loss_kernel(const float* __restrict__ a,
                                                      const float* __restrict__ b,
                                                      float* __restrict__ out) {
    extern __shared__ float ring[];            // NRING * 8192 floats (96 KB)

    __shared__ __align__(8) unsigned long long mbar_store[NRING];
    __shared__ float s_v[16];
    __shared__ float s_s[16];
    __shared__ int   s_c[16];
    __shared__ int   s_idx;

    const int t = threadIdx.x;
    const int warp = t >> 5, lane = t & 31;    // warps 0..15
    const int cta = blockIdx.x;
    const int npair  = (NSLICE - cta + NCTA - 1) / NCTA;   // 3 or 4
    const int nslice = 2 * npair;
    const int nchunk = 2 * nslice;                          // 12 or 16

    const uint32_t mb0 = smem_u32(&mbar_store[0]);
    if (t == 0) {
        #pragma unroll
        for (int r = 0; r < NRING; ++r) mbar_init(mb0 + 8u * r, 1);
    }
    __syncthreads();

    // chunk k: pair (k>>2), tensor ((k>>1)&1), half (k&1)
    auto chunk_src = [&](int k) -> const float* {
        int p = k >> 2, which = (k >> 1) & 1, half = k & 1;
        const float* base = which ? b : a;
        return base + (size_t)(cta + p * NCTA) * HW + (size_t)half * CHUNK_FLOATS;
    };

    if (t == 0) {                              // prefill all ring slots
        #pragma unroll
        for (int k = 0; k < NRING; ++k) {
            mbar_arrive_expect(mb0 + 8u * k, CHUNK_BYTES);
            bulk_g2s(smem_u32(ring + k * CHUNK_FLOATS), chunk_src(k),
                     CHUNK_BYTES, mb0 + 8u * k);
        }
    }

    float acc = 0.0f;       // meaningful in t==0 only
    float prev_d = 0.0f;

    for (int m = 0; m < nslice; ++m) {
        const int k0 = 2 * m, k1 = 2 * m + 1;
        const int slot0 = k0 % NRING, slot1 = k1 % NRING;

        // ---------- pass 1: load 32 elems to regs, value-only max ------------
        float4 v[8];
        mbar_wait(mb0 + 8u * slot0, (k0 / NRING) & 1);
        {
            const float4* p = (const float4*)(ring + slot0 * CHUNK_FLOATS);
            v[0] = p[t];            v[1] = p[NTH + t];
            v[2] = p[2 * NTH + t];  v[3] = p[3 * NTH + t];
        }
        mbar_wait(mb0 + 8u * slot1, (k1 / NRING) & 1);
        {
            const float4* p = (const float4*)(ring + slot1 * CHUNK_FLOATS);
            v[4] = p[t];            v[5] = p[NTH + t];
            v[6] = p[2 * NTH + t];  v[7] = p[3 * NTH + t];
        }
        float mymax = max4(v[0]);
        #pragma unroll
        for (int j = 1; j < 8; ++j) mymax = fmaxf(mymax, max4(v[j]));

        float wmax = mymax;
        #pragma unroll
        for (int off = 16; off > 0; off >>= 1)
            wmax = fmaxf(wmax, __shfl_xor_sync(0xffffffffu, wmax, off));
        if (lane == 0) s_v[warp] = wmax;
        if (t == 0) s_idx = 0x7fffffff;
        __syncthreads();                       // S1: ring slots now free

        // refill freed slots ASAP (warp 1; overlaps the reductions below)
        if (t == 32) {
            if (k0 + NRING < nchunk) {
                mbar_arrive_expect(mb0 + 8u * slot0, CHUNK_BYTES);
                bulk_g2s(smem_u32(ring + slot0 * CHUNK_FLOATS),
                         chunk_src(k0 + NRING), CHUNK_BYTES, mb0 + 8u * slot0);
            }
            if (k1 + NRING < nchunk) {
                mbar_arrive_expect(mb0 + 8u * slot1, CHUNK_BYTES);
                bulk_g2s(smem_u32(ring + slot1 * CHUNK_FLOATS),
                         chunk_src(k1 + NRING), CHUNK_BYTES, mb0 + 8u * slot1);
            }
        }

        // block max over the 16 warp maxima, redundantly per warp
        float bv = s_v[lane & 15];
        #pragma unroll
        for (int off = 8; off > 0; off >>= 1)
            bv = fmaxf(bv, __shfl_xor_sync(0xffffffffu, bv, off));

        // rare path: holders of the max rescan registers; lowest flat e wins.
        // e(j, c) = (j<4 ? j*2048 : 8192 + (j-4)*2048) + 4*t + c, ascending in j.
        if (mymax == bv) {
            int my_e = 0x7fffffff;
            #pragma unroll
            for (int j = 7; j >= 0; --j) {     // descending: last write = lowest e
                const int eb = ((j & 3) << 11) + ((j >> 2) << 13) + (t << 2);
                if (v[j].w == bv) my_e = eb + 3;
                if (v[j].z == bv) my_e = eb + 2;
                if (v[j].y == bv) my_e = eb + 1;
                if (v[j].x == bv) my_e = eb;
            }
            atomicMin(&s_idx, my_e);
        }
        __syncthreads();                       // S2: s_idx final
        const int bi = s_idx;

        // ---------- pass 2: masked distance sum from registers ---------------
        const float thr = bv * 0.5f;
        const int ym = bi >> 7;
        const int xm = bi & 127;

        // x = 4*lane + c is slice-invariant per thread
        const int xb = (lane << 2) - xm;
        const float fdx2_0 = (float)(xb * xb);
        const float fdx2_1 = (float)((xb + 1) * (xb + 1));
        const float fdx2_2 = (float)((xb + 2) * (xb + 2));
        const float fdx2_3 = (float)((xb + 3) * (xb + 3));

        float sum = 0.0f;
        int   cnt = 0;
        // y(v[j]) = 16*j + warp  (j 0..7 spans both chunks contiguously in y)
        #pragma unroll
        for (int j = 0; j < 8; ++j) {
            const int dy = (j << 4) + warp - ym;
            const float fdy2 = (float)(dy * dy);
            float d0 = fsqrt_approx(fdy2 + fdx2_0);
            float d1 = fsqrt_approx(fdy2 + fdx2_1);
            float d2 = fsqrt_approx(fdy2 + fdx2_2);
            float d3 = fsqrt_approx(fdy2 + fdx2_3);
            if (v[j].x > thr) { sum += d0; ++cnt; }
            if (v[j].y > thr) { sum += d1; ++cnt; }
            if (v[j].z > thr) { sum += d2; ++cnt; }
            if (v[j].w > thr) { sum += d3; ++cnt; }
        }
        #pragma unroll
        for (int off = 16; off > 0; off >>= 1) {
            sum += __shfl_down_sync(0xffffffffu, sum, off);
            cnt += __shfl_down_sync(0xffffffffu, cnt, off);
        }
        if (lane == 0) { s_s[warp] = sum; s_c[warp] = cnt; }
        __syncthreads();                       // S3: all partials written

        // warp 0 reduces in parallel; shadowed by other warps entering pass 1
        if (warp == 0) {
            float S = s_s[lane & 15];
            float C = (float)s_c[lane & 15];
            #pragma unroll
            for (int off = 8; off > 0; off >>= 1) {
                S += __shfl_xor_sync(0xffffffffu, S, off);
                C += __shfl_xor_sync(0xffffffffu, C, off);
            }
            if (lane == 0) {
                float d;
                if (bv > 0.0f) {
                    d = (C > 0.0f) ? (S / C) / MAX_DIST : 1.0f;
                } else {
                    d = 0.0f;
                }
                if (m & 1) acc += fabsf(prev_d - d);   // pair done: |d_a - d_b|
                else       prev_d = d;
            }
        }
        // s_v/s_s/s_idx rewrites of the next slice are separated from all
        // reads of this slice by S1..S3 of the next iteration.
    }

    // ---------- fused finalize: one atomic per CTA; last CTA writes + resets
    if (t == 0) {
        atomicAdd(&g_acc, acc);
        __threadfence();
        unsigned int v = atomicAdd(&g_done, 1u);
        if (v == NCTA - 1) {
            float total = atomicAdd(&g_acc, 0.0f);   // serialized read after all adds
            out[0] = total / 17.0f / 64.0f;
            g_acc = 0.0f;                            // restore invariant for next run
            __threadfence();
            g_done = 0u;
        }
    }
}

extern "C" void kernel_launch(void* const* d_in, const int* in_sizes, int n_in,
                              void* d_out, int out_size) {
    const float* a = (const float*)d_in[0];   // output heatmaps [64,17,128,128] f32
    const float* b = (const float*)d_in[1];   // target heatmaps [64,17,128,128] f32
    (void)in_sizes; (void)n_in; (void)out_size;

    const int smem_bytes = NRING * CHUNK_BYTES;   // 96 KB per CTA

    static bool attr_set = false;
    if (!attr_set) {
        cudaFuncSetAttribute(loss_kernel,
                             cudaFuncAttributeMaxDynamicSharedMemorySize, smem_bytes);
        attr_set = true;
    }

    loss_kernel<<<NCTA, NTH, smem_bytes>>>(a, b, (float*)d_out);
}